// round 2
// baseline (speedup 1.0000x reference)
#include <cuda_runtime.h>
#include <math.h>
#include <stdint.h>

// ---------------------------------------------------------------------------
// ModernEqProp: x_emb = x@embed_w^T + b ; 30x { LN -> tanh(GEMM1) -> GEMM2 +
// residual } ; out = h@head_w^T + head_b.  All GEMMs are NT (both operands
// K-major).  Round-1 baseline: fp32 tiled SGEMM (guaranteed-accuracy), fused
// epilogues, device-global scratch.
// ---------------------------------------------------------------------------

#define BM 128
#define BN 128
#define BKK 16
#define TM 8
#define TN 8
#define NTHR 256

static const int BATCH = 4096;
static const int DIN   = 784;
static const int HDIM  = 1024;
static const int FFN   = 4096;
static const int DOUT  = 1000;
static const int STEPS = 30;

__device__ float g_xemb[4096 * 1024];
__device__ float g_h[4096 * 1024];
__device__ float g_hn[4096 * 1024];
__device__ float g_t[4096ULL * 4096];

// Epilogue kinds:
// 0: C = acc + bias
// 1: C = acc + bias, also C2 = same (embed writes x_emb and h0)
// 2: C = tanh(acc + bias)
// 3: C = 0.5*C_old + 0.5*(acc + bias + C2)   (residual update of h)
template <int EPI, bool GN>
__global__ __launch_bounds__(NTHR, 2)
void sgemm_nt(int M, int N, int K,
              const float* __restrict__ A,   // [M,K] row-major
              const float* __restrict__ Bm,  // [N,K] row-major
              const float* __restrict__ bias,
              float* __restrict__ C,         // [M,N]
              float* __restrict__ C2)        // [M,N] (EPI 1/3)
{
    __shared__ float As[BKK][BM + 4];
    __shared__ float Bs[BKK][BN + 4];

    const int tid = threadIdx.x;
    const int tx = tid & 15;        // 0..15 -> N
    const int ty = tid >> 4;        // 0..15 -> M
    const int bn0 = blockIdx.x * BN;
    const int bm0 = blockIdx.y * BM;

    const int lrow = tid >> 2;           // 0..63
    const int lc4  = (tid & 3) << 2;     // 0,4,8,12

    float acc[TM][TN];
#pragma unroll
    for (int i = 0; i < TM; i++)
#pragma unroll
        for (int j = 0; j < TN; j++) acc[i][j] = 0.0f;

    const float* Aptr = A + (size_t)bm0 * K;
    const float* Bptr = Bm + (size_t)bn0 * K;

    for (int k0 = 0; k0 < K; k0 += BKK) {
        // load A tile (128 x 16), store transposed
#pragma unroll
        for (int r = 0; r < 2; r++) {
            int row = lrow + r * 64;
            float4 v = *(const float4*)(Aptr + (size_t)row * K + k0 + lc4);
            As[lc4 + 0][row] = v.x;
            As[lc4 + 1][row] = v.y;
            As[lc4 + 2][row] = v.z;
            As[lc4 + 3][row] = v.w;
        }
        // load B tile (128 x 16), store transposed; guard rows for N=1000
#pragma unroll
        for (int r = 0; r < 2; r++) {
            int row = lrow + r * 64;
            float4 v = make_float4(0.f, 0.f, 0.f, 0.f);
            if (!GN || (bn0 + row) < N)
                v = *(const float4*)(Bptr + (size_t)row * K + k0 + lc4);
            Bs[lc4 + 0][row] = v.x;
            Bs[lc4 + 1][row] = v.y;
            Bs[lc4 + 2][row] = v.z;
            Bs[lc4 + 3][row] = v.w;
        }
        __syncthreads();

#pragma unroll
        for (int k = 0; k < BKK; k++) {
            float a0[TM], b0[TN];
            *(float4*)&a0[0] = *(const float4*)&As[k][ty * TM];
            *(float4*)&a0[4] = *(const float4*)&As[k][ty * TM + 4];
            *(float4*)&b0[0] = *(const float4*)&Bs[k][tx * TN];
            *(float4*)&b0[4] = *(const float4*)&Bs[k][tx * TN + 4];
#pragma unroll
            for (int i = 0; i < TM; i++)
#pragma unroll
                for (int j = 0; j < TN; j++)
                    acc[i][j] = fmaf(a0[i], b0[j], acc[i][j]);
        }
        __syncthreads();
    }

    // epilogue
    const int cm0 = bm0 + ty * TM;
    const int cn0 = bn0 + tx * TN;
#pragma unroll
    for (int i = 0; i < TM; i++) {
        const int m = cm0 + i;
        float* crow = C + (size_t)m * N;
#pragma unroll
        for (int j = 0; j < TN; j++) {
            const int n = cn0 + j;
            if (GN && n >= N) continue;
            float v = acc[i][j] + bias[n];
            if (EPI == 2) v = tanhf(v);
            if (EPI == 3) {
                float xv = C2[(size_t)m * N + n];
                float hv = crow[n];
                v = 0.5f * hv + 0.5f * (v + xv);
            }
            crow[n] = v;
            if (EPI == 1) C2[(size_t)m * N + n] = v;
        }
    }
}

// LayerNorm over H=1024, one block per row.
__global__ __launch_bounds__(256)
void layernorm_k(const float* __restrict__ h,
                 const float* __restrict__ w,
                 const float* __restrict__ b,
                 float* __restrict__ out)
{
    const int row = blockIdx.x;
    const int tid = threadIdx.x;  // 256 threads, 4 floats each
    const float4* hp = (const float4*)(h + (size_t)row * 1024);
    float4 v = hp[tid];
    float s  = v.x + v.y + v.z + v.w;
    float ss = v.x * v.x + v.y * v.y + v.z * v.z + v.w * v.w;

    // warp reduce
#pragma unroll
    for (int o = 16; o > 0; o >>= 1) {
        s  += __shfl_xor_sync(0xffffffffu, s, o);
        ss += __shfl_xor_sync(0xffffffffu, ss, o);
    }
    __shared__ float rs_[8], rss_[8];
    const int lane = tid & 31, wid = tid >> 5;
    if (lane == 0) { rs_[wid] = s; rss_[wid] = ss; }
    __syncthreads();
    if (wid == 0) {
        s  = rs_[lane & 7];
        ss = rss_[lane & 7];
#pragma unroll
        for (int o = 4; o > 0; o >>= 1) {
            s  += __shfl_xor_sync(0xffffffffu, s, o);
            ss += __shfl_xor_sync(0xffffffffu, ss, o);
        }
        if (lane == 0) { rs_[0] = s; rss_[0] = ss; }
    }
    __syncthreads();
    const float mu  = rs_[0] * (1.0f / 1024.0f);
    const float var = rss_[0] * (1.0f / 1024.0f) - mu * mu;
    const float rstd = rsqrtf(var + 1e-5f);

    float4 wv = ((const float4*)w)[tid];
    float4 bv = ((const float4*)b)[tid];
    float4 o4;
    o4.x = (v.x - mu) * rstd * wv.x + bv.x;
    o4.y = (v.y - mu) * rstd * wv.y + bv.y;
    o4.z = (v.z - mu) * rstd * wv.z + bv.z;
    o4.w = (v.w - mu) * rstd * wv.w + bv.w;
    ((float4*)(out + (size_t)row * 1024))[tid] = o4;
}

static inline int cdiv(int a, int b) { return (a + b - 1) / b; }

extern "C" void kernel_launch(void* const* d_in, const int* in_sizes, int n_in,
                              void* d_out, int out_size)
{
    const float* x       = (const float*)d_in[0];
    const float* embed_w = (const float*)d_in[1];
    const float* embed_b = (const float*)d_in[2];
    const float* W1_w    = (const float*)d_in[3];
    const float* W1_b    = (const float*)d_in[4];
    const float* W2_w    = (const float*)d_in[5];
    const float* W2_b    = (const float*)d_in[6];
    const float* norm_w  = (const float*)d_in[7];
    const float* norm_b  = (const float*)d_in[8];
    const float* head_w  = (const float*)d_in[9];
    const float* head_b  = (const float*)d_in[10];
    float* out = (float*)d_out;

    float *xemb, *h, *hn, *t;
    cudaGetSymbolAddress((void**)&xemb, g_xemb);
    cudaGetSymbolAddress((void**)&h,    g_h);
    cudaGetSymbolAddress((void**)&hn,   g_hn);
    cudaGetSymbolAddress((void**)&t,    g_t);

    // embed: x_emb = x @ embed_w^T + embed_b ; h0 = x_emb
    {
        dim3 grid(HDIM / BN, BATCH / BM);
        sgemm_nt<1, false><<<grid, NTHR>>>(BATCH, HDIM, DIN, x, embed_w,
                                           embed_b, xemb, h);
    }

    for (int s = 0; s < STEPS; s++) {
        layernorm_k<<<BATCH, 256>>>(h, norm_w, norm_b, hn);

        // ffn_hidden = tanh(hn @ W1^T + b1)   [4096, 4096]
        {
            dim3 grid(FFN / BN, BATCH / BM);
            sgemm_nt<2, false><<<grid, NTHR>>>(BATCH, FFN, HDIM, hn, W1_w,
                                               W1_b, t, nullptr);
        }
        // h = 0.5*h + 0.5*(t @ W2^T + b2 + x_emb)   [4096, 1024]
        {
            dim3 grid(HDIM / BN, BATCH / BM);
            sgemm_nt<3, false><<<grid, NTHR>>>(BATCH, HDIM, FFN, t, W2_w,
                                               W2_b, h, xemb);
        }
    }

    // out = h @ head_w^T + head_b   [4096, 1000]  (N-guarded)
    {
        dim3 grid(cdiv(DOUT, BN), BATCH / BM);
        sgemm_nt<0, true><<<grid, NTHR>>>(BATCH, DOUT, HDIM, h, head_w,
                                          head_b, out, nullptr);
    }
}

// round 8
// speedup vs baseline: 2.0869x; 2.0869x over previous
#include <cuda_runtime.h>
#include <cuda_bf16.h>
#include <math.h>
#include <stdint.h>

// ---------------------------------------------------------------------------
// ModernEqProp on GB300 (plain compute_103 PTX target -> no tcgen05).
// Big per-step GEMMs run on mma.sync.m16n8k16 bf16 tensor cores with bf16x3
// (hi/lo split) emulated-fp32 accuracy. Embed/head stay on fp32 SGEMM.
// ---------------------------------------------------------------------------

static const int BATCH = 4096;
static const int DIN   = 784;
static const int HDIM  = 1024;
static const int FFN   = 4096;
static const int DOUT  = 1000;
static const int STEPS = 30;

// ------------------------- device scratch (no allocs) ----------------------
__device__ __align__(256) float g_xemb[4096 * 1024];
__device__ __align__(256) float g_h[4096 * 1024];
__device__ __align__(256) __nv_bfloat16 g_hnh[4096 * 1024];
__device__ __align__(256) __nv_bfloat16 g_hnl[4096 * 1024];
__device__ __align__(256) __nv_bfloat16 g_th[4096ULL * 4096];
__device__ __align__(256) __nv_bfloat16 g_tl[4096ULL * 4096];
__device__ __align__(256) __nv_bfloat16 g_w1h[4096 * 1024];
__device__ __align__(256) __nv_bfloat16 g_w1l[4096 * 1024];
__device__ __align__(256) __nv_bfloat16 g_w2h[4096 * 1024];
__device__ __align__(256) __nv_bfloat16 g_w2l[4096 * 1024];

// ------------------------------ PTX helpers --------------------------------
__device__ __forceinline__ uint32_t smem_u32(const void* p) {
    uint32_t a;
    asm("{ .reg .u64 t; cvta.to.shared.u64 t, %1; cvt.u32.u64 %0, t; }"
        : "=r"(a) : "l"(p));
    return a;
}
__device__ __forceinline__ void cp16(uint32_t dst, const void* src) {
    asm volatile("cp.async.cg.shared.global [%0], [%1], 16;"
                 :: "r"(dst), "l"(src) : "memory");
}
__device__ __forceinline__ void cp_commit() {
    asm volatile("cp.async.commit_group;" ::: "memory");
}
template <int N>
__device__ __forceinline__ void cp_wait() {
    asm volatile("cp.async.wait_group %0;" :: "n"(N) : "memory");
}
__device__ __forceinline__ void ldm_x4(uint32_t& r0, uint32_t& r1,
                                       uint32_t& r2, uint32_t& r3,
                                       uint32_t addr) {
    asm volatile("ldmatrix.sync.aligned.m8n8.x4.shared.b16 {%0,%1,%2,%3}, [%4];"
                 : "=r"(r0), "=r"(r1), "=r"(r2), "=r"(r3) : "r"(addr));
}
__device__ __forceinline__ void mma16816(float* c, const uint32_t* a,
                                         const uint32_t* b) {
    asm volatile(
        "mma.sync.aligned.m16n8k16.row.col.f32.bf16.bf16.f32 "
        "{%0,%1,%2,%3}, {%4,%5,%6,%7}, {%8,%9}, {%0,%1,%2,%3};"
        : "+f"(c[0]), "+f"(c[1]), "+f"(c[2]), "+f"(c[3])
        : "r"(a[0]), "r"(a[1]), "r"(a[2]), "r"(a[3]), "r"(b[0]), "r"(b[1]));
}

// --------------------------- mma.sync GEMM ---------------------------------
// C[M,N] = (Ah+Al) @ (Bh+Bl)^T with A [M,K], B [N,K] bf16 row-major.
// BM=BN=128, BK=32, 3-stage cp.async pipeline, 8 warps (4x2), bf16x3.
// EPI 0: v = tanh(acc + bias[n]) -> ohi/olo bf16 hi/lo (stride Nt)
// EPI 1: h[m,n] = 0.5*h + 0.5*(acc + bias[n] + xemb[m,n])
#define MSTAGES 3
#define LDPAD 40                       // 32 + 8 bf16 (80B row stride)
#define TILE_B (128 * LDPAD * 2)       // 10240 B, one matrix tile
#define MSTAGE_B (4 * TILE_B)          // Ah, Al, Bh, Bl
#define MSMEM_B (MSTAGES * MSTAGE_B)   // 122880 B

__device__ __forceinline__ void load_stage(
    uint32_t st, const __nv_bfloat16* Ah, const __nv_bfloat16* Al,
    const __nv_bfloat16* Bh, const __nv_bfloat16* Bl,
    int K, int bm0, int bn0, int kc, int tid)
{
    const int r  = tid >> 1;            // 0..127
    const int c0 = (tid & 1) * 2;       // chunk 0 or 2
    const __nv_bfloat16* pa0 = Ah + (size_t)(bm0 + r) * K + kc;
    const __nv_bfloat16* pa1 = Al + (size_t)(bm0 + r) * K + kc;
    const __nv_bfloat16* pb0 = Bh + (size_t)(bn0 + r) * K + kc;
    const __nv_bfloat16* pb1 = Bl + (size_t)(bn0 + r) * K + kc;
#pragma unroll
    for (int c = c0; c < c0 + 2; c++) {
        const uint32_t doff = r * (LDPAD * 2) + c * 16;
        cp16(st + 0 * TILE_B + doff, pa0 + c * 8);
        cp16(st + 1 * TILE_B + doff, pa1 + c * 8);
        cp16(st + 2 * TILE_B + doff, pb0 + c * 8);
        cp16(st + 3 * TILE_B + doff, pb1 + c * 8);
    }
}

template <int EPI>
__global__ void __launch_bounds__(256, 1)
tgemm_mma(const __nv_bfloat16* __restrict__ Ah,
          const __nv_bfloat16* __restrict__ Al,
          const __nv_bfloat16* __restrict__ Bh,
          const __nv_bfloat16* __restrict__ Bl,
          int K, int Nt,
          const float* __restrict__ bias,
          float* __restrict__ hbuf,
          const float* __restrict__ xemb,
          __nv_bfloat16* __restrict__ ohi,
          __nv_bfloat16* __restrict__ olo)
{
    extern __shared__ char smem[];
    const uint32_t sb = smem_u32(smem);
    const int tid  = threadIdx.x;
    const int wid  = tid >> 5;
    const int lane = tid & 31;
    const int warp_m = wid >> 1;   // 0..3 -> 32 rows each
    const int warp_n = wid & 1;    // 0..1 -> 64 cols each
    const int bn0 = blockIdx.x * 128;
    const int bm0 = blockIdx.y * 128;
    const int nIter = K >> 5;

    // ldmatrix lane address offsets (bytes within a tile)
    const int mat = lane >> 3;
    const int arow = warp_m * 32 + (lane & 7) + ((mat & 1) * 8);
    const int acol16 = mat >> 1;
    const uint32_t aoff = arow * (LDPAD * 2) + acol16 * 16;
    const int brow = warp_n * 64 + (lane & 7) + ((mat >> 1) * 8);
    const int bcol16 = mat & 1;
    const uint32_t boff = brow * (LDPAD * 2) + bcol16 * 16;

    float acc[2][8][4];
#pragma unroll
    for (int i = 0; i < 2; i++)
#pragma unroll
        for (int j = 0; j < 8; j++)
#pragma unroll
            for (int q = 0; q < 4; q++) acc[i][j][q] = 0.0f;

    // prologue: fill MSTAGES-1 stages
#pragma unroll
    for (int s = 0; s < MSTAGES - 1; s++) {
        load_stage(sb + s * MSTAGE_B, Ah, Al, Bh, Bl, K, bm0, bn0, s * 32, tid);
        cp_commit();
    }
    cp_wait<MSTAGES - 2>();
    __syncthreads();

    for (int it = 0; it < nIter; it++) {
        const uint32_t st = sb + (it % MSTAGES) * MSTAGE_B;
        const uint32_t sAh = st;
        const uint32_t sAl = st + TILE_B;
        const uint32_t sBh = st + 2 * TILE_B;
        const uint32_t sBl = st + 3 * TILE_B;

#pragma unroll
        for (int kt = 0; kt < 2; kt++) {
            const uint32_t kby = kt * 32;
            uint32_t ah[2][4], al[2][4];
#pragma unroll
            for (int mi = 0; mi < 2; mi++) {
                ldm_x4(ah[mi][0], ah[mi][1], ah[mi][2], ah[mi][3],
                       sAh + aoff + mi * 16 * (LDPAD * 2) + kby);
                ldm_x4(al[mi][0], al[mi][1], al[mi][2], al[mi][3],
                       sAl + aoff + mi * 16 * (LDPAD * 2) + kby);
            }
            uint32_t bh[4][4], bl[4][4];
#pragma unroll
            for (int nb = 0; nb < 4; nb++) {
                ldm_x4(bh[nb][0], bh[nb][1], bh[nb][2], bh[nb][3],
                       sBh + boff + nb * 16 * (LDPAD * 2) + kby);
                ldm_x4(bl[nb][0], bl[nb][1], bl[nb][2], bl[nb][3],
                       sBl + boff + nb * 16 * (LDPAD * 2) + kby);
            }
#pragma unroll
            for (int nb = 0; nb < 4; nb++) {
#pragma unroll
                for (int hf = 0; hf < 2; hf++) {
                    const int nf = nb * 2 + hf;
#pragma unroll
                    for (int mi = 0; mi < 2; mi++) {
                        mma16816(acc[mi][nf], ah[mi], &bh[nb][hf * 2]);
                        mma16816(acc[mi][nf], ah[mi], &bl[nb][hf * 2]);
                        mma16816(acc[mi][nf], al[mi], &bh[nb][hf * 2]);
                    }
                }
            }
        }

        // issue next stage's loads
        const int nx = it + MSTAGES - 1;
        if (nx < nIter)
            load_stage(sb + (nx % MSTAGES) * MSTAGE_B, Ah, Al, Bh, Bl,
                       K, bm0, bn0, nx * 32, tid);
        cp_commit();
        cp_wait<MSTAGES - 2>();
        __syncthreads();
    }

    // ----------------------------- epilogue --------------------------------
    const int r0 = bm0 + warp_m * 32 + (lane >> 2);
    const int cbase = bn0 + warp_n * 64 + (lane & 3) * 2;
#pragma unroll
    for (int mi = 0; mi < 2; mi++) {
#pragma unroll
        for (int nf = 0; nf < 8; nf++) {
            const int n = cbase + nf * 8;
            const float2 bb = *(const float2*)(bias + n);
#pragma unroll
            for (int half = 0; half < 2; half++) {
                const int m = r0 + mi * 16 + half * 8;
                const float v0r = acc[mi][nf][half * 2 + 0] + bb.x;
                const float v1r = acc[mi][nf][half * 2 + 1] + bb.y;
                const size_t idx = (size_t)m * Nt + n;
                if (EPI == 0) {
                    const float v0 = tanhf(v0r);
                    const float v1 = tanhf(v1r);
                    __nv_bfloat16 h0 = __float2bfloat16_rn(v0);
                    __nv_bfloat16 h1 = __float2bfloat16_rn(v1);
                    __nv_bfloat16 l0 = __float2bfloat16_rn(v0 - __bfloat162float(h0));
                    __nv_bfloat16 l1 = __float2bfloat16_rn(v1 - __bfloat162float(h1));
                    *(__nv_bfloat162*)(ohi + idx) = __halves2bfloat162(h0, h1);
                    *(__nv_bfloat162*)(olo + idx) = __halves2bfloat162(l0, l1);
                } else {
                    const float2 hv = *(const float2*)(hbuf + idx);
                    const float2 xv = *(const float2*)(xemb + idx);
                    float2 o;
                    o.x = 0.5f * hv.x + 0.5f * (v0r + xv.x);
                    o.y = 0.5f * hv.y + 0.5f * (v1r + xv.y);
                    *(float2*)(hbuf + idx) = o;
                }
            }
        }
    }
}

// ----------------------- fp32 SGEMM (embed / head) -------------------------
#define BM 128
#define BN 128
#define BKK 16
#define TMv 8
#define TNv 8
#define NTHR 256

// EPI 0: C = acc + bias (GN guard on N). EPI 1: C = acc + bias; C2 = same.
template <int EPI, bool GN>
__global__ __launch_bounds__(NTHR, 2)
void sgemm_nt(int M, int N, int K,
              const float* __restrict__ A,
              const float* __restrict__ Bm,
              const float* __restrict__ bias,
              float* __restrict__ C,
              float* __restrict__ C2)
{
    __shared__ float As[BKK][BM + 4];
    __shared__ float Bs[BKK][BN + 4];

    const int tid = threadIdx.x;
    const int tx = tid & 15;
    const int ty = tid >> 4;
    const int bn0 = blockIdx.x * BN;
    const int bm0 = blockIdx.y * BM;
    const int lrow = tid >> 2;
    const int lc4  = (tid & 3) << 2;

    float acc[TMv][TNv];
#pragma unroll
    for (int i = 0; i < TMv; i++)
#pragma unroll
        for (int j = 0; j < TNv; j++) acc[i][j] = 0.0f;

    const float* Aptr = A + (size_t)bm0 * K;
    const float* Bptr = Bm + (size_t)bn0 * K;

    for (int k0 = 0; k0 < K; k0 += BKK) {
#pragma unroll
        for (int r = 0; r < 2; r++) {
            int row = lrow + r * 64;
            float4 v = *(const float4*)(Aptr + (size_t)row * K + k0 + lc4);
            As[lc4 + 0][row] = v.x; As[lc4 + 1][row] = v.y;
            As[lc4 + 2][row] = v.z; As[lc4 + 3][row] = v.w;
        }
#pragma unroll
        for (int r = 0; r < 2; r++) {
            int row = lrow + r * 64;
            float4 v = make_float4(0.f, 0.f, 0.f, 0.f);
            if (!GN || (bn0 + row) < N)
                v = *(const float4*)(Bptr + (size_t)row * K + k0 + lc4);
            Bs[lc4 + 0][row] = v.x; Bs[lc4 + 1][row] = v.y;
            Bs[lc4 + 2][row] = v.z; Bs[lc4 + 3][row] = v.w;
        }
        __syncthreads();
#pragma unroll
        for (int k = 0; k < BKK; k++) {
            float a0[TMv], b0[TNv];
            *(float4*)&a0[0] = *(const float4*)&As[k][ty * TMv];
            *(float4*)&a0[4] = *(const float4*)&As[k][ty * TMv + 4];
            *(float4*)&b0[0] = *(const float4*)&Bs[k][tx * TNv];
            *(float4*)&b0[4] = *(const float4*)&Bs[k][tx * TNv + 4];
#pragma unroll
            for (int i = 0; i < TMv; i++)
#pragma unroll
                for (int j = 0; j < TNv; j++)
                    acc[i][j] = fmaf(a0[i], b0[j], acc[i][j]);
        }
        __syncthreads();
    }

    const int cm0 = bm0 + ty * TMv;
    const int cn0 = bn0 + tx * TNv;
#pragma unroll
    for (int i = 0; i < TMv; i++) {
        const int m = cm0 + i;
        float* crow = C + (size_t)m * N;
#pragma unroll
        for (int j = 0; j < TNv; j++) {
            const int n = cn0 + j;
            if (GN && n >= N) continue;
            float v = acc[i][j] + bias[n];
            crow[n] = v;
            if (EPI == 1) C2[(size_t)m * N + n] = v;
        }
    }
}

// --------------------- LayerNorm -> bf16 hi/lo (H=1024) --------------------
__global__ __launch_bounds__(256)
void layernorm_k(const float* __restrict__ h,
                 const float* __restrict__ w,
                 const float* __restrict__ b,
                 __nv_bfloat16* __restrict__ ohi,
                 __nv_bfloat16* __restrict__ olo)
{
    const int row = blockIdx.x;
    const int tid = threadIdx.x;
    const float4* hp = (const float4*)(h + (size_t)row * 1024);
    float4 v = hp[tid];
    float s  = v.x + v.y + v.z + v.w;
    float ss = v.x * v.x + v.y * v.y + v.z * v.z + v.w * v.w;
#pragma unroll
    for (int o = 16; o > 0; o >>= 1) {
        s  += __shfl_xor_sync(0xffffffffu, s, o);
        ss += __shfl_xor_sync(0xffffffffu, ss, o);
    }
    __shared__ float rs_[8], rss_[8];
    const int lane = tid & 31, wid = tid >> 5;
    if (lane == 0) { rs_[wid] = s; rss_[wid] = ss; }
    __syncthreads();
    if (wid == 0) {
        s  = rs_[lane & 7];
        ss = rss_[lane & 7];
#pragma unroll
        for (int o = 4; o > 0; o >>= 1) {
            s  += __shfl_xor_sync(0xffffffffu, s, o);
            ss += __shfl_xor_sync(0xffffffffu, ss, o);
        }
        if (lane == 0) { rs_[0] = s; rss_[0] = ss; }
    }
    __syncthreads();
    const float mu  = rs_[0] * (1.0f / 1024.0f);
    const float var = rss_[0] * (1.0f / 1024.0f) - mu * mu;
    const float rstd = rsqrtf(var + 1e-5f);

    float4 wv = ((const float4*)w)[tid];
    float4 bv = ((const float4*)b)[tid];
    float o0 = (v.x - mu) * rstd * wv.x + bv.x;
    float o1 = (v.y - mu) * rstd * wv.y + bv.y;
    float o2 = (v.z - mu) * rstd * wv.z + bv.z;
    float o3 = (v.w - mu) * rstd * wv.w + bv.w;

    __nv_bfloat16 h0 = __float2bfloat16_rn(o0), h1 = __float2bfloat16_rn(o1);
    __nv_bfloat16 h2 = __float2bfloat16_rn(o2), h3 = __float2bfloat16_rn(o3);
    __nv_bfloat16 l0 = __float2bfloat16_rn(o0 - __bfloat162float(h0));
    __nv_bfloat16 l1 = __float2bfloat16_rn(o1 - __bfloat162float(h1));
    __nv_bfloat16 l2 = __float2bfloat16_rn(o2 - __bfloat162float(h2));
    __nv_bfloat16 l3 = __float2bfloat16_rn(o3 - __bfloat162float(h3));

    __nv_bfloat162* oh = (__nv_bfloat162*)(ohi + (size_t)row * 1024 + tid * 4);
    __nv_bfloat162* ol = (__nv_bfloat162*)(olo + (size_t)row * 1024 + tid * 4);
    oh[0] = __halves2bfloat162(h0, h1);
    oh[1] = __halves2bfloat162(h2, h3);
    ol[0] = __halves2bfloat162(l0, l1);
    ol[1] = __halves2bfloat162(l2, l3);
}

// --------------------- fp32 -> bf16 hi/lo splitter -------------------------
__global__ __launch_bounds__(256)
void split_k(const float4* __restrict__ src,
             __nv_bfloat162* __restrict__ hi,
             __nv_bfloat162* __restrict__ lo, int n4)
{
    int i = blockIdx.x * blockDim.x + threadIdx.x;
    if (i >= n4) return;
    float4 v = src[i];
    __nv_bfloat16 h0 = __float2bfloat16_rn(v.x), h1 = __float2bfloat16_rn(v.y);
    __nv_bfloat16 h2 = __float2bfloat16_rn(v.z), h3 = __float2bfloat16_rn(v.w);
    __nv_bfloat16 l0 = __float2bfloat16_rn(v.x - __bfloat162float(h0));
    __nv_bfloat16 l1 = __float2bfloat16_rn(v.y - __bfloat162float(h1));
    __nv_bfloat16 l2 = __float2bfloat16_rn(v.z - __bfloat162float(h2));
    __nv_bfloat16 l3 = __float2bfloat16_rn(v.w - __bfloat162float(h3));
    hi[i * 2 + 0] = __halves2bfloat162(h0, h1);
    hi[i * 2 + 1] = __halves2bfloat162(h2, h3);
    lo[i * 2 + 0] = __halves2bfloat162(l0, l1);
    lo[i * 2 + 1] = __halves2bfloat162(l2, l3);
}

// ------------------------------- host side ---------------------------------
static inline int cdiv(int a, int b) { return (a + b - 1) / b; }

extern "C" void kernel_launch(void* const* d_in, const int* in_sizes, int n_in,
                              void* d_out, int out_size)
{
    const float* x       = (const float*)d_in[0];
    const float* embed_w = (const float*)d_in[1];
    const float* embed_b = (const float*)d_in[2];
    const float* W1_w    = (const float*)d_in[3];
    const float* W1_b    = (const float*)d_in[4];
    const float* W2_w    = (const float*)d_in[5];
    const float* W2_b    = (const float*)d_in[6];
    const float* norm_w  = (const float*)d_in[7];
    const float* norm_b  = (const float*)d_in[8];
    const float* head_w  = (const float*)d_in[9];
    const float* head_b  = (const float*)d_in[10];
    float* out = (float*)d_out;
    (void)in_sizes; (void)n_in; (void)out_size;

    float *xemb, *h;
    __nv_bfloat16 *hnh, *hnl, *th, *tl, *w1h, *w1l, *w2h, *w2l;
    cudaGetSymbolAddress((void**)&xemb, g_xemb);
    cudaGetSymbolAddress((void**)&h,    g_h);
    cudaGetSymbolAddress((void**)&hnh,  g_hnh);
    cudaGetSymbolAddress((void**)&hnl,  g_hnl);
    cudaGetSymbolAddress((void**)&th,   g_th);
    cudaGetSymbolAddress((void**)&tl,   g_tl);
    cudaGetSymbolAddress((void**)&w1h,  g_w1h);
    cudaGetSymbolAddress((void**)&w1l,  g_w1l);
    cudaGetSymbolAddress((void**)&w2h,  g_w2h);
    cudaGetSymbolAddress((void**)&w2l,  g_w2l);

    cudaFuncSetAttribute(tgemm_mma<0>,
                         cudaFuncAttributeMaxDynamicSharedMemorySize, MSMEM_B);
    cudaFuncSetAttribute(tgemm_mma<1>,
                         cudaFuncAttributeMaxDynamicSharedMemorySize, MSMEM_B);

    // Split weights to bf16 hi/lo.
    {
        int n4 = (FFN * HDIM) / 4;
        split_k<<<cdiv(n4, 256), 256>>>((const float4*)W1_w,
                                        (__nv_bfloat162*)w1h,
                                        (__nv_bfloat162*)w1l, n4);
        split_k<<<cdiv(n4, 256), 256>>>((const float4*)W2_w,
                                        (__nv_bfloat162*)w2h,
                                        (__nv_bfloat162*)w2l, n4);
    }

    // embed: x_emb = x @ embed_w^T + embed_b ; h0 = x_emb
    {
        dim3 grid(HDIM / BN, BATCH / BM);
        sgemm_nt<1, false><<<grid, NTHR>>>(BATCH, HDIM, DIN, x, embed_w,
                                           embed_b, xemb, h);
    }

    for (int s = 0; s < STEPS; s++) {
        layernorm_k<<<BATCH, 256>>>(h, norm_w, norm_b, hnh, hnl);

        // t = tanh(hn @ W1^T + b1)  [4096, 4096] -> bf16 hi/lo
        {
            dim3 grid(FFN / 128, BATCH / 128);
            tgemm_mma<0><<<grid, 256, MSMEM_B>>>(hnh, hnl, w1h, w1l,
                                                 HDIM, FFN, W1_b,
                                                 nullptr, nullptr, th, tl);
        }
        // h = 0.5*h + 0.5*(t @ W2^T + b2 + x_emb)  [4096, 1024]
        {
            dim3 grid(HDIM / 128, BATCH / 128);
            tgemm_mma<1><<<grid, 256, MSMEM_B>>>(th, tl, w2h, w2l,
                                                 FFN, HDIM, W2_b,
                                                 h, xemb, nullptr, nullptr);
        }
    }

    // out = h @ head_w^T + head_b   [4096, 1000]
    {
        dim3 grid(cdiv(DOUT, BN), BATCH / BM);
        sgemm_nt<0, true><<<grid, NTHR>>>(BATCH, DOUT, HDIM, h, head_w,
                                          head_b, out, nullptr);
    }
}

// round 10
// speedup vs baseline: 3.6213x; 1.7353x over previous
#include <cuda_runtime.h>
#include <cuda_bf16.h>
#include <cuda_fp16.h>
#include <math.h>
#include <stdint.h>

// ---------------------------------------------------------------------------
// ModernEqProp on GB300 (plain compute_103 PTX target -> no tcgen05).
// Big per-step GEMMs: mma.sync.m16n8k16 fp16 tensor cores, fp16x2 scheme:
//   activations split hi/lo (near-exact), weights rounded to fp16.
//   error ~= 2^-12 (weight rounding), well under the 1e-3 gate.
// Embed/head stay on fp32 SGEMM.
// ---------------------------------------------------------------------------

static const int BATCH = 4096;
static const int DIN   = 784;
static const int HDIM  = 1024;
static const int FFN   = 4096;
static const int DOUT  = 1000;
static const int STEPS = 30;

// ------------------------- device scratch (no allocs) ----------------------
__device__ __align__(256) float g_xemb[4096 * 1024];
__device__ __align__(256) float g_h[4096 * 1024];
__device__ __align__(256) __half g_hnh[4096 * 1024];
__device__ __align__(256) __half g_hnl[4096 * 1024];
__device__ __align__(256) __half g_th[4096ULL * 4096];
__device__ __align__(256) __half g_tl[4096ULL * 4096];
__device__ __align__(256) __half g_w1h[4096 * 1024];
__device__ __align__(256) __half g_w2h[4096 * 1024];

// ------------------------------ PTX helpers --------------------------------
__device__ __forceinline__ uint32_t smem_u32(const void* p) {
    uint32_t a;
    asm("{ .reg .u64 t; cvta.to.shared.u64 t, %1; cvt.u32.u64 %0, t; }"
        : "=r"(a) : "l"(p));
    return a;
}
__device__ __forceinline__ void cp16(uint32_t dst, const void* src) {
    asm volatile("cp.async.cg.shared.global [%0], [%1], 16;"
                 :: "r"(dst), "l"(src) : "memory");
}
__device__ __forceinline__ void cp_commit() {
    asm volatile("cp.async.commit_group;" ::: "memory");
}
template <int N>
__device__ __forceinline__ void cp_wait() {
    asm volatile("cp.async.wait_group %0;" :: "n"(N) : "memory");
}
__device__ __forceinline__ void ldm_x4(uint32_t& r0, uint32_t& r1,
                                       uint32_t& r2, uint32_t& r3,
                                       uint32_t addr) {
    asm volatile("ldmatrix.sync.aligned.m8n8.x4.shared.b16 {%0,%1,%2,%3}, [%4];"
                 : "=r"(r0), "=r"(r1), "=r"(r2), "=r"(r3) : "r"(addr));
}
__device__ __forceinline__ void mma16816h(float* c, const uint32_t* a,
                                          const uint32_t* b) {
    asm volatile(
        "mma.sync.aligned.m16n8k16.row.col.f32.f16.f16.f32 "
        "{%0,%1,%2,%3}, {%4,%5,%6,%7}, {%8,%9}, {%0,%1,%2,%3};"
        : "+f"(c[0]), "+f"(c[1]), "+f"(c[2]), "+f"(c[3])
        : "r"(a[0]), "r"(a[1]), "r"(a[2]), "r"(a[3]), "r"(b[0]), "r"(b[1]));
}

// --------------------------- mma.sync GEMM ---------------------------------
// C[M,N] = (Ah+Al) @ Bh^T, A [M,K] fp16 hi/lo, B [N,K] fp16, row-major.
// BM=BN=128, BK=32, 4-stage cp.async pipeline, 8 warps (4x2), fp16x2.
// EPI 0: v = tanh(acc + bias[n]) -> ohi/olo fp16 hi/lo (stride Nt)
// EPI 1: h[m,n] = 0.5*h + 0.5*(acc + bias[n] + xemb[m,n])
#define MSTAGES 4
#define LDPAD 40                       // 32 + 8 halves (80B row stride)
#define TILE_B (128 * LDPAD * 2)       // 10240 B, one matrix tile
#define MSTAGE_B (3 * TILE_B)          // Ah, Al, Bh
#define MSMEM_B (MSTAGES * MSTAGE_B)   // 122880 B

__device__ __forceinline__ void load_stage(
    uint32_t st, const __half* Ah, const __half* Al, const __half* Bh,
    int K, int bm0, int bn0, int kc, int tid)
{
    const int r  = tid >> 1;            // 0..127
    const int c0 = (tid & 1) * 2;       // chunk 0 or 2
    const __half* pa0 = Ah + (size_t)(bm0 + r) * K + kc;
    const __half* pa1 = Al + (size_t)(bm0 + r) * K + kc;
    const __half* pb0 = Bh + (size_t)(bn0 + r) * K + kc;
#pragma unroll
    for (int c = c0; c < c0 + 2; c++) {
        const uint32_t doff = r * (LDPAD * 2) + c * 16;
        cp16(st + 0 * TILE_B + doff, pa0 + c * 8);
        cp16(st + 1 * TILE_B + doff, pa1 + c * 8);
        cp16(st + 2 * TILE_B + doff, pb0 + c * 8);
    }
}

template <int EPI>
__global__ void __launch_bounds__(256, 1)
tgemm_mma(const __half* __restrict__ Ah,
          const __half* __restrict__ Al,
          const __half* __restrict__ Bh,
          int K, int Nt,
          const float* __restrict__ bias,
          float* __restrict__ hbuf,
          const float* __restrict__ xemb,
          __half* __restrict__ ohi,
          __half* __restrict__ olo)
{
    extern __shared__ char smem[];
    const uint32_t sb = smem_u32(smem);
    const int tid  = threadIdx.x;
    const int wid  = tid >> 5;
    const int lane = tid & 31;
    const int warp_m = wid >> 1;   // 0..3 -> 32 rows each
    const int warp_n = wid & 1;    // 0..1 -> 64 cols each
    const int bn0 = blockIdx.x * 128;
    const int bm0 = blockIdx.y * 128;
    const int nIter = K >> 5;

    // ldmatrix lane address offsets (bytes within a tile)
    const int mat = lane >> 3;
    const int arow = warp_m * 32 + (lane & 7) + ((mat & 1) * 8);
    const int acol16 = mat >> 1;
    const uint32_t aoff = arow * (LDPAD * 2) + acol16 * 16;
    const int brow = warp_n * 64 + (lane & 7) + ((mat >> 1) * 8);
    const int bcol16 = mat & 1;
    const uint32_t boff = brow * (LDPAD * 2) + bcol16 * 16;

    float acc[2][8][4];
#pragma unroll
    for (int i = 0; i < 2; i++)
#pragma unroll
        for (int j = 0; j < 8; j++)
#pragma unroll
            for (int q = 0; q < 4; q++) acc[i][j][q] = 0.0f;

    // prologue: fill MSTAGES-1 stages
#pragma unroll
    for (int s = 0; s < MSTAGES - 1; s++) {
        load_stage(sb + s * MSTAGE_B, Ah, Al, Bh, K, bm0, bn0, s * 32, tid);
        cp_commit();
    }
    cp_wait<MSTAGES - 2>();
    __syncthreads();

    for (int it = 0; it < nIter; it++) {
        const uint32_t st = sb + (it % MSTAGES) * MSTAGE_B;
        const uint32_t sAh = st;
        const uint32_t sAl = st + TILE_B;
        const uint32_t sBh = st + 2 * TILE_B;

#pragma unroll
        for (int kt = 0; kt < 2; kt++) {
            const uint32_t kby = kt * 32;
            uint32_t ah[2][4], al[2][4];
#pragma unroll
            for (int mi = 0; mi < 2; mi++) {
                ldm_x4(ah[mi][0], ah[mi][1], ah[mi][2], ah[mi][3],
                       sAh + aoff + mi * 16 * (LDPAD * 2) + kby);
                ldm_x4(al[mi][0], al[mi][1], al[mi][2], al[mi][3],
                       sAl + aoff + mi * 16 * (LDPAD * 2) + kby);
            }
            uint32_t bh[4][4];
#pragma unroll
            for (int nb = 0; nb < 4; nb++) {
                ldm_x4(bh[nb][0], bh[nb][1], bh[nb][2], bh[nb][3],
                       sBh + boff + nb * 16 * (LDPAD * 2) + kby);
            }
#pragma unroll
            for (int nb = 0; nb < 4; nb++) {
#pragma unroll
                for (int hf = 0; hf < 2; hf++) {
                    const int nf = nb * 2 + hf;
#pragma unroll
                    for (int mi = 0; mi < 2; mi++) {
                        mma16816h(acc[mi][nf], ah[mi], &bh[nb][hf * 2]);
                        mma16816h(acc[mi][nf], al[mi], &bh[nb][hf * 2]);
                    }
                }
            }
        }

        // issue next stage's loads
        const int nx = it + MSTAGES - 1;
        if (nx < nIter)
            load_stage(sb + (nx % MSTAGES) * MSTAGE_B, Ah, Al, Bh,
                       K, bm0, bn0, nx * 32, tid);
        cp_commit();
        cp_wait<MSTAGES - 2>();
        __syncthreads();
    }

    // ----------------------------- epilogue --------------------------------
    const int r0 = bm0 + warp_m * 32 + (lane >> 2);
    const int cbase = bn0 + warp_n * 64 + (lane & 3) * 2;
#pragma unroll
    for (int mi = 0; mi < 2; mi++) {
#pragma unroll
        for (int nf = 0; nf < 8; nf++) {
            const int n = cbase + nf * 8;
            const float2 bb = *(const float2*)(bias + n);
#pragma unroll
            for (int half_ = 0; half_ < 2; half_++) {
                const int m = r0 + mi * 16 + half_ * 8;
                const float v0r = acc[mi][nf][half_ * 2 + 0] + bb.x;
                const float v1r = acc[mi][nf][half_ * 2 + 1] + bb.y;
                const size_t idx = (size_t)m * Nt + n;
                if (EPI == 0) {
                    const float v0 = tanhf(v0r);
                    const float v1 = tanhf(v1r);
                    __half h0 = __float2half_rn(v0);
                    __half h1 = __float2half_rn(v1);
                    __half l0 = __float2half_rn(v0 - __half2float(h0));
                    __half l1 = __float2half_rn(v1 - __half2float(h1));
                    *(__half2*)(ohi + idx) = __halves2half2(h0, h1);
                    *(__half2*)(olo + idx) = __halves2half2(l0, l1);
                } else {
                    const float2 hv = *(const float2*)(hbuf + idx);
                    const float2 xv = *(const float2*)(xemb + idx);
                    float2 o;
                    o.x = 0.5f * hv.x + 0.5f * (v0r + xv.x);
                    o.y = 0.5f * hv.y + 0.5f * (v1r + xv.y);
                    *(float2*)(hbuf + idx) = o;
                }
            }
        }
    }
}

// ----------------------- fp32 SGEMM (embed / head) -------------------------
#define BM 128
#define BN 128
#define BKK 16
#define TMv 8
#define TNv 8
#define NTHR 256

// EPI 0: C = acc + bias (GN guard on N). EPI 1: C = acc + bias; C2 = same.
template <int EPI, bool GN>
__global__ __launch_bounds__(NTHR, 2)
void sgemm_nt(int M, int N, int K,
              const float* __restrict__ A,
              const float* __restrict__ Bm,
              const float* __restrict__ bias,
              float* __restrict__ C,
              float* __restrict__ C2)
{
    __shared__ float As[BKK][BM + 4];
    __shared__ float Bs[BKK][BN + 4];

    const int tid = threadIdx.x;
    const int tx = tid & 15;
    const int ty = tid >> 4;
    const int bn0 = blockIdx.x * BN;
    const int bm0 = blockIdx.y * BM;
    const int lrow = tid >> 2;
    const int lc4  = (tid & 3) << 2;

    float acc[TMv][TNv];
#pragma unroll
    for (int i = 0; i < TMv; i++)
#pragma unroll
        for (int j = 0; j < TNv; j++) acc[i][j] = 0.0f;

    const float* Aptr = A + (size_t)bm0 * K;
    const float* Bptr = Bm + (size_t)bn0 * K;

    for (int k0 = 0; k0 < K; k0 += BKK) {
#pragma unroll
        for (int r = 0; r < 2; r++) {
            int row = lrow + r * 64;
            float4 v = *(const float4*)(Aptr + (size_t)row * K + k0 + lc4);
            As[lc4 + 0][row] = v.x; As[lc4 + 1][row] = v.y;
            As[lc4 + 2][row] = v.z; As[lc4 + 3][row] = v.w;
        }
#pragma unroll
        for (int r = 0; r < 2; r++) {
            int row = lrow + r * 64;
            float4 v = make_float4(0.f, 0.f, 0.f, 0.f);
            if (!GN || (bn0 + row) < N)
                v = *(const float4*)(Bptr + (size_t)row * K + k0 + lc4);
            Bs[lc4 + 0][row] = v.x; Bs[lc4 + 1][row] = v.y;
            Bs[lc4 + 2][row] = v.z; Bs[lc4 + 3][row] = v.w;
        }
        __syncthreads();
#pragma unroll
        for (int k = 0; k < BKK; k++) {
            float a0[TMv], b0[TNv];
            *(float4*)&a0[0] = *(const float4*)&As[k][ty * TMv];
            *(float4*)&a0[4] = *(const float4*)&As[k][ty * TMv + 4];
            *(float4*)&b0[0] = *(const float4*)&Bs[k][tx * TNv];
            *(float4*)&b0[4] = *(const float4*)&Bs[k][tx * TNv + 4];
#pragma unroll
            for (int i = 0; i < TMv; i++)
#pragma unroll
                for (int j = 0; j < TNv; j++)
                    acc[i][j] = fmaf(a0[i], b0[j], acc[i][j]);
        }
        __syncthreads();
    }

    const int cm0 = bm0 + ty * TMv;
    const int cn0 = bn0 + tx * TNv;
#pragma unroll
    for (int i = 0; i < TMv; i++) {
        const int m = cm0 + i;
        float* crow = C + (size_t)m * N;
#pragma unroll
        for (int j = 0; j < TNv; j++) {
            const int n = cn0 + j;
            if (GN && n >= N) continue;
            float v = acc[i][j] + bias[n];
            crow[n] = v;
            if (EPI == 1) C2[(size_t)m * N + n] = v;
        }
    }
}

// --------------------- LayerNorm -> fp16 hi/lo (H=1024) --------------------
__global__ __launch_bounds__(256)
void layernorm_k(const float* __restrict__ h,
                 const float* __restrict__ w,
                 const float* __restrict__ b,
                 __half* __restrict__ ohi,
                 __half* __restrict__ olo)
{
    const int row = blockIdx.x;
    const int tid = threadIdx.x;
    const float4* hp = (const float4*)(h + (size_t)row * 1024);
    float4 v = hp[tid];
    float s  = v.x + v.y + v.z + v.w;
    float ss = v.x * v.x + v.y * v.y + v.z * v.z + v.w * v.w;
#pragma unroll
    for (int o = 16; o > 0; o >>= 1) {
        s  += __shfl_xor_sync(0xffffffffu, s, o);
        ss += __shfl_xor_sync(0xffffffffu, ss, o);
    }
    __shared__ float rs_[8], rss_[8];
    const int lane = tid & 31, wid = tid >> 5;
    if (lane == 0) { rs_[wid] = s; rss_[wid] = ss; }
    __syncthreads();
    if (wid == 0) {
        s  = rs_[lane & 7];
        ss = rss_[lane & 7];
#pragma unroll
        for (int o = 4; o > 0; o >>= 1) {
            s  += __shfl_xor_sync(0xffffffffu, s, o);
            ss += __shfl_xor_sync(0xffffffffu, ss, o);
        }
        if (lane == 0) { rs_[0] = s; rss_[0] = ss; }
    }
    __syncthreads();
    const float mu  = rs_[0] * (1.0f / 1024.0f);
    const float var = rss_[0] * (1.0f / 1024.0f) - mu * mu;
    const float rstd = rsqrtf(var + 1e-5f);

    float4 wv = ((const float4*)w)[tid];
    float4 bv = ((const float4*)b)[tid];
    float o0 = (v.x - mu) * rstd * wv.x + bv.x;
    float o1 = (v.y - mu) * rstd * wv.y + bv.y;
    float o2 = (v.z - mu) * rstd * wv.z + bv.z;
    float o3 = (v.w - mu) * rstd * wv.w + bv.w;

    __half h0 = __float2half_rn(o0), h1 = __float2half_rn(o1);
    __half h2 = __float2half_rn(o2), h3 = __float2half_rn(o3);
    __half l0 = __float2half_rn(o0 - __half2float(h0));
    __half l1 = __float2half_rn(o1 - __half2float(h1));
    __half l2 = __float2half_rn(o2 - __half2float(h2));
    __half l3 = __float2half_rn(o3 - __half2float(h3));

    __half2* oh = (__half2*)(ohi + (size_t)row * 1024 + tid * 4);
    __half2* ol = (__half2*)(olo + (size_t)row * 1024 + tid * 4);
    oh[0] = __halves2half2(h0, h1);
    oh[1] = __halves2half2(h2, h3);
    ol[0] = __halves2half2(l0, l1);
    ol[1] = __halves2half2(l2, l3);
}

// --------------------- fp32 -> fp16 weight rounding ------------------------
__global__ __launch_bounds__(256)
void wcvt_k(const float4* __restrict__ src, __half2* __restrict__ dst, int n4)
{
    int i = blockIdx.x * blockDim.x + threadIdx.x;
    if (i >= n4) return;
    float4 v = src[i];
    dst[i * 2 + 0] = __halves2half2(__float2half_rn(v.x), __float2half_rn(v.y));
    dst[i * 2 + 1] = __halves2half2(__float2half_rn(v.z), __float2half_rn(v.w));
}

// ------------------------------- host side ---------------------------------
static inline int cdiv(int a, int b) { return (a + b - 1) / b; }

extern "C" void kernel_launch(void* const* d_in, const int* in_sizes, int n_in,
                              void* d_out, int out_size)
{
    const float* x       = (const float*)d_in[0];
    const float* embed_w = (const float*)d_in[1];
    const float* embed_b = (const float*)d_in[2];
    const float* W1_w    = (const float*)d_in[3];
    const float* W1_b    = (const float*)d_in[4];
    const float* W2_w    = (const float*)d_in[5];
    const float* W2_b    = (const float*)d_in[6];
    const float* norm_w  = (const float*)d_in[7];
    const float* norm_b  = (const float*)d_in[8];
    const float* head_w  = (const float*)d_in[9];
    const float* head_b  = (const float*)d_in[10];
    float* out = (float*)d_out;
    (void)in_sizes; (void)n_in; (void)out_size;

    float *xemb, *h;
    __half *hnh, *hnl, *th, *tl, *w1h, *w2h;
    cudaGetSymbolAddress((void**)&xemb, g_xemb);
    cudaGetSymbolAddress((void**)&h,    g_h);
    cudaGetSymbolAddress((void**)&hnh,  g_hnh);
    cudaGetSymbolAddress((void**)&hnl,  g_hnl);
    cudaGetSymbolAddress((void**)&th,   g_th);
    cudaGetSymbolAddress((void**)&tl,   g_tl);
    cudaGetSymbolAddress((void**)&w1h,  g_w1h);
    cudaGetSymbolAddress((void**)&w2h,  g_w2h);

    cudaFuncSetAttribute(tgemm_mma<0>,
                         cudaFuncAttributeMaxDynamicSharedMemorySize, MSMEM_B);
    cudaFuncSetAttribute(tgemm_mma<1>,
                         cudaFuncAttributeMaxDynamicSharedMemorySize, MSMEM_B);

    // Round weights to fp16.
    {
        int n4 = (FFN * HDIM) / 4;
        wcvt_k<<<cdiv(n4, 256), 256>>>((const float4*)W1_w, (__half2*)w1h, n4);
        wcvt_k<<<cdiv(n4, 256), 256>>>((const float4*)W2_w, (__half2*)w2h, n4);
    }

    // embed: x_emb = x @ embed_w^T + embed_b ; h0 = x_emb
    {
        dim3 grid(HDIM / BN, BATCH / BM);
        sgemm_nt<1, false><<<grid, NTHR>>>(BATCH, HDIM, DIN, x, embed_w,
                                           embed_b, xemb, h);
    }

    for (int s = 0; s < STEPS; s++) {
        layernorm_k<<<BATCH, 256>>>(h, norm_w, norm_b, hnh, hnl);

        // t = tanh(hn @ W1^T + b1)  [4096, 4096] -> fp16 hi/lo
        {
            dim3 grid(FFN / 128, BATCH / 128);
            tgemm_mma<0><<<grid, 256, MSMEM_B>>>(hnh, hnl, w1h,
                                                 HDIM, FFN, W1_b,
                                                 nullptr, nullptr, th, tl);
        }
        // h = 0.5*h + 0.5*(t @ W2^T + b2 + x_emb)  [4096, 1024]
        {
            dim3 grid(HDIM / 128, BATCH / 128);
            tgemm_mma<1><<<grid, 256, MSMEM_B>>>(th, tl, w2h,
                                                 FFN, HDIM, W2_b,
                                                 h, xemb, nullptr, nullptr);
        }
    }

    // out = h @ head_w^T + head_b   [4096, 1000]
    {
        dim3 grid(cdiv(DOUT, BN), BATCH / BM);
        sgemm_nt<0, true><<<grid, NTHR>>>(BATCH, DOUT, HDIM, h, head_w,
                                          head_b, out, nullptr);
    }
}

// round 11
// speedup vs baseline: 5.2880x; 1.4603x over previous
#include <cuda_runtime.h>
#include <cuda_bf16.h>
#include <cuda_fp16.h>
#include <math.h>
#include <stdint.h>

// ---------------------------------------------------------------------------
// ModernEqProp on GB300 (plain compute_103 PTX target -> no tcgen05).
// Big per-step GEMMs: pure fp16 mma.sync.m16n8k16 (fp32 accumulate).
// Weights AND activations rounded to fp16; measured error calibration says
// combined rounding lands ~1.5e-4 << 1e-3 gate (GEMM averaging cancels
// per-element rounding). Embed/head stay on fp32 SGEMM.
// ---------------------------------------------------------------------------

static const int BATCH = 4096;
static const int DIN   = 784;
static const int HDIM  = 1024;
static const int FFN   = 4096;
static const int DOUT  = 1000;
static const int STEPS = 30;

// ------------------------- device scratch (no allocs) ----------------------
__device__ __align__(256) float g_xemb[4096 * 1024];
__device__ __align__(256) float g_h[4096 * 1024];
__device__ __align__(256) __half g_hn[4096 * 1024];
__device__ __align__(256) __half g_t[4096ULL * 4096];
__device__ __align__(256) __half g_w1h[4096 * 1024];
__device__ __align__(256) __half g_w2h[4096 * 1024];

// ------------------------------ PTX helpers --------------------------------
__device__ __forceinline__ uint32_t smem_u32(const void* p) {
    uint32_t a;
    asm("{ .reg .u64 t; cvta.to.shared.u64 t, %1; cvt.u32.u64 %0, t; }"
        : "=r"(a) : "l"(p));
    return a;
}
__device__ __forceinline__ void cp16(uint32_t dst, const void* src) {
    asm volatile("cp.async.cg.shared.global [%0], [%1], 16;"
                 :: "r"(dst), "l"(src) : "memory");
}
__device__ __forceinline__ void cp_commit() {
    asm volatile("cp.async.commit_group;" ::: "memory");
}
template <int N>
__device__ __forceinline__ void cp_wait() {
    asm volatile("cp.async.wait_group %0;" :: "n"(N) : "memory");
}
__device__ __forceinline__ void ldm_x4(uint32_t& r0, uint32_t& r1,
                                       uint32_t& r2, uint32_t& r3,
                                       uint32_t addr) {
    asm volatile("ldmatrix.sync.aligned.m8n8.x4.shared.b16 {%0,%1,%2,%3}, [%4];"
                 : "=r"(r0), "=r"(r1), "=r"(r2), "=r"(r3) : "r"(addr));
}
__device__ __forceinline__ void mma16816h(float* c, const uint32_t* a,
                                          const uint32_t* b) {
    asm volatile(
        "mma.sync.aligned.m16n8k16.row.col.f32.f16.f16.f32 "
        "{%0,%1,%2,%3}, {%4,%5,%6,%7}, {%8,%9}, {%0,%1,%2,%3};"
        : "+f"(c[0]), "+f"(c[1]), "+f"(c[2]), "+f"(c[3])
        : "r"(a[0]), "r"(a[1]), "r"(a[2]), "r"(a[3]), "r"(b[0]), "r"(b[1]));
}

// --------------------------- mma.sync GEMM ---------------------------------
// C[M,N] = A @ B^T, A [M,K] fp16, B [N,K] fp16, row-major.
// BM=BN=128, BK=32, 4-stage cp.async pipeline, 8 warps (4x2).
// EPI 0: v = tanh(acc + bias[n]) -> o (fp16, stride Nt)
// EPI 1: h[m,n] = 0.5*h + 0.5*(acc + bias[n] + xemb[m,n])
#define MSTAGES 4
#define LDPAD 40                       // 32 + 8 halves (80B row stride)
#define TILE_B (128 * LDPAD * 2)       // 10240 B, one matrix tile
#define MSTAGE_B (2 * TILE_B)          // A, B
#define MSMEM_B (MSTAGES * MSTAGE_B)   // 81920 B

__device__ __forceinline__ void load_stage(
    uint32_t st, const __half* A, const __half* B,
    int K, int bm0, int bn0, int kc, int tid)
{
    const int r  = tid >> 1;            // 0..127
    const int c0 = (tid & 1) * 2;       // chunk 0 or 2
    const __half* pa = A + (size_t)(bm0 + r) * K + kc;
    const __half* pb = B + (size_t)(bn0 + r) * K + kc;
#pragma unroll
    for (int c = c0; c < c0 + 2; c++) {
        const uint32_t doff = r * (LDPAD * 2) + c * 16;
        cp16(st + 0 * TILE_B + doff, pa + c * 8);
        cp16(st + 1 * TILE_B + doff, pb + c * 8);
    }
}

template <int EPI>
__global__ void __launch_bounds__(256, 1)
tgemm_mma(const __half* __restrict__ A,
          const __half* __restrict__ B,
          int K, int Nt,
          const float* __restrict__ bias,
          float* __restrict__ hbuf,
          const float* __restrict__ xemb,
          __half* __restrict__ o)
{
    extern __shared__ char smem[];
    const uint32_t sb = smem_u32(smem);
    const int tid  = threadIdx.x;
    const int wid  = tid >> 5;
    const int lane = tid & 31;
    const int warp_m = wid >> 1;   // 0..3 -> 32 rows each
    const int warp_n = wid & 1;    // 0..1 -> 64 cols each
    const int bn0 = blockIdx.x * 128;
    const int bm0 = blockIdx.y * 128;
    const int nIter = K >> 5;

    // ldmatrix lane address offsets (bytes within a tile)
    const int mat = lane >> 3;
    const int arow = warp_m * 32 + (lane & 7) + ((mat & 1) * 8);
    const int acol16 = mat >> 1;
    const uint32_t aoff = arow * (LDPAD * 2) + acol16 * 16;
    const int brow = warp_n * 64 + (lane & 7) + ((mat >> 1) * 8);
    const int bcol16 = mat & 1;
    const uint32_t boff = brow * (LDPAD * 2) + bcol16 * 16;

    float acc[2][8][4];
#pragma unroll
    for (int i = 0; i < 2; i++)
#pragma unroll
        for (int j = 0; j < 8; j++)
#pragma unroll
            for (int q = 0; q < 4; q++) acc[i][j][q] = 0.0f;

    // prologue: fill MSTAGES-1 stages
#pragma unroll
    for (int s = 0; s < MSTAGES - 1; s++) {
        load_stage(sb + s * MSTAGE_B, A, B, K, bm0, bn0, s * 32, tid);
        cp_commit();
    }
    cp_wait<MSTAGES - 2>();
    __syncthreads();

    for (int it = 0; it < nIter; it++) {
        const uint32_t st = sb + (it % MSTAGES) * MSTAGE_B;
        const uint32_t sA = st;
        const uint32_t sB = st + TILE_B;

#pragma unroll
        for (int kt = 0; kt < 2; kt++) {
            const uint32_t kby = kt * 32;
            uint32_t ar[2][4];
#pragma unroll
            for (int mi = 0; mi < 2; mi++)
                ldm_x4(ar[mi][0], ar[mi][1], ar[mi][2], ar[mi][3],
                       sA + aoff + mi * 16 * (LDPAD * 2) + kby);
            uint32_t br[4][4];
#pragma unroll
            for (int nb = 0; nb < 4; nb++)
                ldm_x4(br[nb][0], br[nb][1], br[nb][2], br[nb][3],
                       sB + boff + nb * 16 * (LDPAD * 2) + kby);
#pragma unroll
            for (int nb = 0; nb < 4; nb++)
#pragma unroll
                for (int hf = 0; hf < 2; hf++) {
                    const int nf = nb * 2 + hf;
#pragma unroll
                    for (int mi = 0; mi < 2; mi++)
                        mma16816h(acc[mi][nf], ar[mi], &br[nb][hf * 2]);
                }
        }

        // issue next stage's loads
        const int nx = it + MSTAGES - 1;
        if (nx < nIter)
            load_stage(sb + (nx % MSTAGES) * MSTAGE_B, A, B,
                       K, bm0, bn0, nx * 32, tid);
        cp_commit();
        cp_wait<MSTAGES - 2>();
        __syncthreads();
    }

    // ----------------------------- epilogue --------------------------------
    const int r0 = bm0 + warp_m * 32 + (lane >> 2);
    const int cbase = bn0 + warp_n * 64 + (lane & 3) * 2;
#pragma unroll
    for (int mi = 0; mi < 2; mi++) {
#pragma unroll
        for (int nf = 0; nf < 8; nf++) {
            const int n = cbase + nf * 8;
            const float2 bb = *(const float2*)(bias + n);
#pragma unroll
            for (int half_ = 0; half_ < 2; half_++) {
                const int m = r0 + mi * 16 + half_ * 8;
                const float v0r = acc[mi][nf][half_ * 2 + 0] + bb.x;
                const float v1r = acc[mi][nf][half_ * 2 + 1] + bb.y;
                const size_t idx = (size_t)m * Nt + n;
                if (EPI == 0) {
                    *(__half2*)(o + idx) =
                        __halves2half2(__float2half_rn(tanhf(v0r)),
                                       __float2half_rn(tanhf(v1r)));
                } else {
                    const float2 hv = *(const float2*)(hbuf + idx);
                    const float2 xv = *(const float2*)(xemb + idx);
                    float2 ov;
                    ov.x = 0.5f * hv.x + 0.5f * (v0r + xv.x);
                    ov.y = 0.5f * hv.y + 0.5f * (v1r + xv.y);
                    *(float2*)(hbuf + idx) = ov;
                }
            }
        }
    }
}

// ----------------------- fp32 SGEMM (embed / head) -------------------------
#define BM 128
#define BN 128
#define BKK 16
#define TMv 8
#define TNv 8
#define NTHR 256

// EPI 0: C = acc + bias (GN guard on N). EPI 1: C = acc + bias; C2 = same.
template <int EPI, bool GN>
__global__ __launch_bounds__(NTHR, 2)
void sgemm_nt(int M, int N, int K,
              const float* __restrict__ A,
              const float* __restrict__ Bm,
              const float* __restrict__ bias,
              float* __restrict__ C,
              float* __restrict__ C2)
{
    __shared__ float As[BKK][BM + 4];
    __shared__ float Bs[BKK][BN + 4];

    const int tid = threadIdx.x;
    const int tx = tid & 15;
    const int ty = tid >> 4;
    const int bn0 = blockIdx.x * BN;
    const int bm0 = blockIdx.y * BM;
    const int lrow = tid >> 2;
    const int lc4  = (tid & 3) << 2;

    float acc[TMv][TNv];
#pragma unroll
    for (int i = 0; i < TMv; i++)
#pragma unroll
        for (int j = 0; j < TNv; j++) acc[i][j] = 0.0f;

    const float* Aptr = A + (size_t)bm0 * K;
    const float* Bptr = Bm + (size_t)bn0 * K;

    for (int k0 = 0; k0 < K; k0 += BKK) {
#pragma unroll
        for (int r = 0; r < 2; r++) {
            int row = lrow + r * 64;
            float4 v = *(const float4*)(Aptr + (size_t)row * K + k0 + lc4);
            As[lc4 + 0][row] = v.x; As[lc4 + 1][row] = v.y;
            As[lc4 + 2][row] = v.z; As[lc4 + 3][row] = v.w;
        }
#pragma unroll
        for (int r = 0; r < 2; r++) {
            int row = lrow + r * 64;
            float4 v = make_float4(0.f, 0.f, 0.f, 0.f);
            if (!GN || (bn0 + row) < N)
                v = *(const float4*)(Bptr + (size_t)row * K + k0 + lc4);
            Bs[lc4 + 0][row] = v.x; Bs[lc4 + 1][row] = v.y;
            Bs[lc4 + 2][row] = v.z; Bs[lc4 + 3][row] = v.w;
        }
        __syncthreads();
#pragma unroll
        for (int k = 0; k < BKK; k++) {
            float a0[TMv], b0[TNv];
            *(float4*)&a0[0] = *(const float4*)&As[k][ty * TMv];
            *(float4*)&a0[4] = *(const float4*)&As[k][ty * TMv + 4];
            *(float4*)&b0[0] = *(const float4*)&Bs[k][tx * TNv];
            *(float4*)&b0[4] = *(const float4*)&Bs[k][tx * TNv + 4];
#pragma unroll
            for (int i = 0; i < TMv; i++)
#pragma unroll
                for (int j = 0; j < TNv; j++)
                    acc[i][j] = fmaf(a0[i], b0[j], acc[i][j]);
        }
        __syncthreads();
    }

    const int cm0 = bm0 + ty * TMv;
    const int cn0 = bn0 + tx * TNv;
#pragma unroll
    for (int i = 0; i < TMv; i++) {
        const int m = cm0 + i;
        float* crow = C + (size_t)m * N;
#pragma unroll
        for (int j = 0; j < TNv; j++) {
            const int n = cn0 + j;
            if (GN && n >= N) continue;
            float v = acc[i][j] + bias[n];
            crow[n] = v;
            if (EPI == 1) C2[(size_t)m * N + n] = v;
        }
    }
}

// --------------------- LayerNorm -> fp16 (H=1024) --------------------------
__global__ __launch_bounds__(256)
void layernorm_k(const float* __restrict__ h,
                 const float* __restrict__ w,
                 const float* __restrict__ b,
                 __half* __restrict__ o)
{
    const int row = blockIdx.x;
    const int tid = threadIdx.x;
    const float4* hp = (const float4*)(h + (size_t)row * 1024);
    float4 v = hp[tid];
    float s  = v.x + v.y + v.z + v.w;
    float ss = v.x * v.x + v.y * v.y + v.z * v.z + v.w * v.w;
#pragma unroll
    for (int of = 16; of > 0; of >>= 1) {
        s  += __shfl_xor_sync(0xffffffffu, s, of);
        ss += __shfl_xor_sync(0xffffffffu, ss, of);
    }
    __shared__ float rs_[8], rss_[8];
    const int lane = tid & 31, wid = tid >> 5;
    if (lane == 0) { rs_[wid] = s; rss_[wid] = ss; }
    __syncthreads();
    if (wid == 0) {
        s  = rs_[lane & 7];
        ss = rss_[lane & 7];
#pragma unroll
        for (int of = 4; of > 0; of >>= 1) {
            s  += __shfl_xor_sync(0xffffffffu, s, of);
            ss += __shfl_xor_sync(0xffffffffu, ss, of);
        }
        if (lane == 0) { rs_[0] = s; rss_[0] = ss; }
    }
    __syncthreads();
    const float mu  = rs_[0] * (1.0f / 1024.0f);
    const float var = rss_[0] * (1.0f / 1024.0f) - mu * mu;
    const float rstd = rsqrtf(var + 1e-5f);

    float4 wv = ((const float4*)w)[tid];
    float4 bv = ((const float4*)b)[tid];
    float o0 = (v.x - mu) * rstd * wv.x + bv.x;
    float o1 = (v.y - mu) * rstd * wv.y + bv.y;
    float o2 = (v.z - mu) * rstd * wv.z + bv.z;
    float o3 = (v.w - mu) * rstd * wv.w + bv.w;

    __half2* op = (__half2*)(o + (size_t)row * 1024 + tid * 4);
    op[0] = __halves2half2(__float2half_rn(o0), __float2half_rn(o1));
    op[1] = __halves2half2(__float2half_rn(o2), __float2half_rn(o3));
}

// --------------------- fp32 -> fp16 weight rounding ------------------------
__global__ __launch_bounds__(256)
void wcvt_k(const float4* __restrict__ src, __half2* __restrict__ dst, int n4)
{
    int i = blockIdx.x * blockDim.x + threadIdx.x;
    if (i >= n4) return;
    float4 v = src[i];
    dst[i * 2 + 0] = __halves2half2(__float2half_rn(v.x), __float2half_rn(v.y));
    dst[i * 2 + 1] = __halves2half2(__float2half_rn(v.z), __float2half_rn(v.w));
}

// ------------------------------- host side ---------------------------------
static inline int cdiv(int a, int b) { return (a + b - 1) / b; }

extern "C" void kernel_launch(void* const* d_in, const int* in_sizes, int n_in,
                              void* d_out, int out_size)
{
    const float* x       = (const float*)d_in[0];
    const float* embed_w = (const float*)d_in[1];
    const float* embed_b = (const float*)d_in[2];
    const float* W1_w    = (const float*)d_in[3];
    const float* W1_b    = (const float*)d_in[4];
    const float* W2_w    = (const float*)d_in[5];
    const float* W2_b    = (const float*)d_in[6];
    const float* norm_w  = (const float*)d_in[7];
    const float* norm_b  = (const float*)d_in[8];
    const float* head_w  = (const float*)d_in[9];
    const float* head_b  = (const float*)d_in[10];
    float* out = (float*)d_out;
    (void)in_sizes; (void)n_in; (void)out_size;

    float *xemb, *h;
    __half *hn, *t, *w1h, *w2h;
    cudaGetSymbolAddress((void**)&xemb, g_xemb);
    cudaGetSymbolAddress((void**)&h,    g_h);
    cudaGetSymbolAddress((void**)&hn,   g_hn);
    cudaGetSymbolAddress((void**)&t,    g_t);
    cudaGetSymbolAddress((void**)&w1h,  g_w1h);
    cudaGetSymbolAddress((void**)&w2h,  g_w2h);

    cudaFuncSetAttribute(tgemm_mma<0>,
                         cudaFuncAttributeMaxDynamicSharedMemorySize, MSMEM_B);
    cudaFuncSetAttribute(tgemm_mma<1>,
                         cudaFuncAttributeMaxDynamicSharedMemorySize, MSMEM_B);

    // Round weights to fp16.
    {
        int n4 = (FFN * HDIM) / 4;
        wcvt_k<<<cdiv(n4, 256), 256>>>((const float4*)W1_w, (__half2*)w1h, n4);
        wcvt_k<<<cdiv(n4, 256), 256>>>((const float4*)W2_w, (__half2*)w2h, n4);
    }

    // embed: x_emb = x @ embed_w^T + embed_b ; h0 = x_emb
    {
        dim3 grid(HDIM / BN, BATCH / BM);
        sgemm_nt<1, false><<<grid, NTHR>>>(BATCH, HDIM, DIN, x, embed_w,
                                           embed_b, xemb, h);
    }

    for (int s = 0; s < STEPS; s++) {
        layernorm_k<<<BATCH, 256>>>(h, norm_w, norm_b, hn);

        // t = tanh(hn @ W1^T + b1)  [4096, 4096] fp16
        {
            dim3 grid(FFN / 128, BATCH / 128);
            tgemm_mma<0><<<grid, 256, MSMEM_B>>>(hn, w1h, HDIM, FFN, W1_b,
                                                 nullptr, nullptr, t);
        }
        // h = 0.5*h + 0.5*(t @ W2^T + b2 + x_emb)  [4096, 1024]
        {
            dim3 grid(HDIM / 128, BATCH / 128);
            tgemm_mma<1><<<grid, 256, MSMEM_B>>>(t, w2h, FFN, HDIM, W2_b,
                                                 h, xemb, nullptr);
        }
    }

    // out = h @ head_w^T + head_b   [4096, 1000]
    {
        dim3 grid(cdiv(DOUT, BN), BATCH / BM);
        sgemm_nt<0, true><<<grid, NTHR>>>(BATCH, DOUT, HDIM, h, head_w,
                                          head_b, out, nullptr);
    }
}

// round 17
// speedup vs baseline: 6.1146x; 1.1563x over previous
#include <cuda_runtime.h>
#include <cuda_fp16.h>
#include <math.h>
#include <stdint.h>

// ---------------------------------------------------------------------------
// ModernEqProp on GB300 (plain compute_103 target -> legacy mma.sync path).
// ALL GEMMs on fp16 m16n8k16 tensor cores (fp32 accum), 2 CTAs/SM for
// prologue/epilogue overlap. LN + tanh + residual fused into epilogues.
// (Re-bench of round-15 submission: container infra failure, kernel untested.)
// ---------------------------------------------------------------------------

static const int BATCH = 4096;
static const int DIN   = 784;
static const int DINP  = 800;    // padded to 32 | K
static const int HDIM  = 1024;
static const int FFN   = 4096;
static const int DOUT  = 1000;
static const int STEPS = 30;

// ------------------------- device scratch (no allocs) ----------------------
__device__ __align__(256) float  g_xemb[4096 * 1024];
__device__ __align__(256) float  g_h[4096 * 1024];
__device__ __align__(256) __half g_hn[4096 * 1024];
__device__ __align__(256) __half g_t[4096ULL * 4096];
__device__ __align__(256) __half g_w1h[4096 * 1024];
__device__ __align__(256) __half g_w2h[4096 * 1024];
__device__ __align__(256) __half g_xp[4096 * 800];     // x fp16, K-padded
__device__ __align__(256) __half g_ewp[1024 * 800];    // embed_w fp16, padded
__device__ __align__(256) __half g_hwp[1024 * 1024];   // head_w fp16, N-padded
__device__ __align__(256) float  g_hbp[1024];          // head_b padded
__device__ __align__(256) __half g_hf[4096 * 1024];    // h fp16 (head input)

// ------------------------------ PTX helpers --------------------------------
__device__ __forceinline__ uint32_t smem_u32(const void* p) {
    uint32_t a;
    asm("{ .reg .u64 t; cvta.to.shared.u64 t, %1; cvt.u32.u64 %0, t; }"
        : "=r"(a) : "l"(p));
    return a;
}
__device__ __forceinline__ void cp16(uint32_t dst, const void* src) {
    asm volatile("cp.async.cg.shared.global [%0], [%1], 16;"
                 :: "r"(dst), "l"(src) : "memory");
}
__device__ __forceinline__ void cp_commit() {
    asm volatile("cp.async.commit_group;" ::: "memory");
}
template <int N>
__device__ __forceinline__ void cp_wait() {
    asm volatile("cp.async.wait_group %0;" :: "n"(N) : "memory");
}
__device__ __forceinline__ void ldm_x4(uint32_t& r0, uint32_t& r1,
                                       uint32_t& r2, uint32_t& r3,
                                       uint32_t addr) {
    asm volatile("ldmatrix.sync.aligned.m8n8.x4.shared.b16 {%0,%1,%2,%3}, [%4];"
                 : "=r"(r0), "=r"(r1), "=r"(r2), "=r"(r3) : "r"(addr));
}
__device__ __forceinline__ void mma16816h(float* c, const uint32_t* a,
                                          const uint32_t* b) {
    asm volatile(
        "mma.sync.aligned.m16n8k16.row.col.f32.f16.f16.f32 "
        "{%0,%1,%2,%3}, {%4,%5,%6,%7}, {%8,%9}, {%0,%1,%2,%3};"
        : "+f"(c[0]), "+f"(c[1]), "+f"(c[2]), "+f"(c[3])
        : "r"(a[0]), "r"(a[1]), "r"(a[2]), "r"(a[3]), "r"(b[0]), "r"(b[1]));
}

// --------------------------- mma.sync GEMM ---------------------------------
// C[M,N] = A @ B^T, A [M,K] fp16, B [N,K] fp16, row-major.
// BM=BN=128, BK=32, 4-stage cp.async pipeline, 8 warps (4x2), 2 CTAs/SM.
// EPI 0: o[m,n]    = fp16(tanh(acc + bias[n]))                      (Nt)
// EPI 1: fw0[m,n]  = 0.5*fw0 + 0.5*(acc + bias[n] + frd[m,n])       (Nt)
// EPI 2: fw0[m,n]  = fw1[m,n] = acc + bias[n]                       (Nt)
// EPI 3: fw0[m,n]  = acc + bias[n], guarded n < NOUT, stride NOUT
#define MSTAGES 4
#define LDPAD 40                       // 32 + 8 halves (80B row stride)
#define TILE_B (128 * LDPAD * 2)       // 10240 B per matrix tile
#define MSTAGE_B (2 * TILE_B)
#define MSMEM_B (MSTAGES * MSTAGE_B)   // 81920 B

__device__ __forceinline__ void load_stage(
    uint32_t st, const __half* A, const __half* B,
    int K, int bm0, int bn0, int kc, int tid)
{
    const int r  = tid >> 1;            // 0..127
    const int c0 = (tid & 1) * 2;       // chunk 0 or 2
    const __half* pa = A + (size_t)(bm0 + r) * K + kc;
    const __half* pb = B + (size_t)(bn0 + r) * K + kc;
#pragma unroll
    for (int c = c0; c < c0 + 2; c++) {
        const uint32_t doff = r * (LDPAD * 2) + c * 16;
        cp16(st + 0 * TILE_B + doff, pa + c * 8);
        cp16(st + 1 * TILE_B + doff, pb + c * 8);
    }
}

template <int EPI, int NOUT>
__global__ void __launch_bounds__(256, 2)
tgemm_mma(const __half* __restrict__ A,
          const __half* __restrict__ B,
          int K, int Nt,
          const float* __restrict__ bias,
          float* __restrict__ fw0,
          float* __restrict__ fw1,
          const float* __restrict__ frd,
          __half* __restrict__ o)
{
    extern __shared__ char smem[];
    const uint32_t sb = smem_u32(smem);
    const int tid  = threadIdx.x;
    const int wid  = tid >> 5;
    const int lane = tid & 31;
    const int warp_m = wid >> 1;   // 0..3 -> 32 rows each
    const int warp_n = wid & 1;    // 0..1 -> 64 cols each
    const int bn0 = blockIdx.x * 128;
    const int bm0 = blockIdx.y * 128;
    const int nIter = K >> 5;

    const int mat = lane >> 3;
    const int arow = warp_m * 32 + (lane & 7) + ((mat & 1) * 8);
    const int acol16 = mat >> 1;
    const uint32_t aoff = arow * (LDPAD * 2) + acol16 * 16;
    const int brow = warp_n * 64 + (lane & 7) + ((mat >> 1) * 8);
    const int bcol16 = mat & 1;
    const uint32_t boff = brow * (LDPAD * 2) + bcol16 * 16;

    float acc[2][8][4];
#pragma unroll
    for (int i = 0; i < 2; i++)
#pragma unroll
        for (int j = 0; j < 8; j++)
#pragma unroll
            for (int q = 0; q < 4; q++) acc[i][j][q] = 0.0f;

#pragma unroll
    for (int s = 0; s < MSTAGES - 1; s++) {
        load_stage(sb + s * MSTAGE_B, A, B, K, bm0, bn0, s * 32, tid);
        cp_commit();
    }
    cp_wait<MSTAGES - 2>();
    __syncthreads();

    for (int it = 0; it < nIter; it++) {
        const uint32_t st = sb + (it % MSTAGES) * MSTAGE_B;
        const uint32_t sA = st;
        const uint32_t sB = st + TILE_B;

#pragma unroll
        for (int kt = 0; kt < 2; kt++) {
            const uint32_t kby = kt * 32;
            uint32_t ar[2][4];
#pragma unroll
            for (int mi = 0; mi < 2; mi++)
                ldm_x4(ar[mi][0], ar[mi][1], ar[mi][2], ar[mi][3],
                       sA + aoff + mi * 16 * (LDPAD * 2) + kby);
            uint32_t br[4][4];
#pragma unroll
            for (int nb = 0; nb < 4; nb++)
                ldm_x4(br[nb][0], br[nb][1], br[nb][2], br[nb][3],
                       sB + boff + nb * 16 * (LDPAD * 2) + kby);
#pragma unroll
            for (int nb = 0; nb < 4; nb++)
#pragma unroll
                for (int hf = 0; hf < 2; hf++) {
                    const int nf = nb * 2 + hf;
#pragma unroll
                    for (int mi = 0; mi < 2; mi++)
                        mma16816h(acc[mi][nf], ar[mi], &br[nb][hf * 2]);
                }
        }

        const int nx = it + MSTAGES - 1;
        if (nx < nIter)
            load_stage(sb + (nx % MSTAGES) * MSTAGE_B, A, B,
                       K, bm0, bn0, nx * 32, tid);
        cp_commit();
        cp_wait<MSTAGES - 2>();
        __syncthreads();
    }

    // ----------------------------- epilogue --------------------------------
    const int r0 = bm0 + warp_m * 32 + (lane >> 2);
    const int cbase = bn0 + warp_n * 64 + (lane & 3) * 2;
#pragma unroll
    for (int mi = 0; mi < 2; mi++) {
#pragma unroll
        for (int nf = 0; nf < 8; nf++) {
            const int n = cbase + nf * 8;
            const float2 bb = *(const float2*)(bias + n);
#pragma unroll
            for (int half_ = 0; half_ < 2; half_++) {
                const int m = r0 + mi * 16 + half_ * 8;
                const float v0 = acc[mi][nf][half_ * 2 + 0] + bb.x;
                const float v1 = acc[mi][nf][half_ * 2 + 1] + bb.y;
                const size_t idx = (size_t)m * Nt + n;
                if (EPI == 0) {
                    *(__half2*)(o + idx) =
                        __halves2half2(__float2half_rn(tanhf(v0)),
                                       __float2half_rn(tanhf(v1)));
                } else if (EPI == 1) {
                    const float2 hv = *(const float2*)(fw0 + idx);
                    const float2 xv = *(const float2*)(frd + idx);
                    float2 ov;
                    ov.x = 0.5f * hv.x + 0.5f * (v0 + xv.x);
                    ov.y = 0.5f * hv.y + 0.5f * (v1 + xv.y);
                    *(float2*)(fw0 + idx) = ov;
                } else if (EPI == 2) {
                    float2 ov; ov.x = v0; ov.y = v1;
                    *(float2*)(fw0 + idx) = ov;
                    *(float2*)(fw1 + idx) = ov;
                } else {  // EPI == 3: guarded store, stride NOUT
                    if (n < NOUT) {
                        float2 ov; ov.x = v0; ov.y = v1;
                        *(float2*)(fw0 + (size_t)m * NOUT + n) = ov;
                    }
                }
            }
        }
    }
}

// --------------------- LayerNorm -> fp16 (H=1024) --------------------------
__global__ __launch_bounds__(256)
void layernorm_k(const float* __restrict__ h,
                 const float* __restrict__ w,
                 const float* __restrict__ b,
                 __half* __restrict__ o)
{
    const int row = blockIdx.x;
    const int tid = threadIdx.x;
    const float4* hp = (const float4*)(h + (size_t)row * 1024);
    float4 v = hp[tid];
    float s  = v.x + v.y + v.z + v.w;
    float ss = v.x * v.x + v.y * v.y + v.z * v.z + v.w * v.w;
#pragma unroll
    for (int of = 16; of > 0; of >>= 1) {
        s  += __shfl_xor_sync(0xffffffffu, s, of);
        ss += __shfl_xor_sync(0xffffffffu, ss, of);
    }
    __shared__ float rs_[8], rss_[8];
    const int lane = tid & 31, wid = tid >> 5;
    if (lane == 0) { rs_[wid] = s; rss_[wid] = ss; }
    __syncthreads();
    if (wid == 0) {
        s  = rs_[lane & 7];
        ss = rss_[lane & 7];
#pragma unroll
        for (int of = 4; of > 0; of >>= 1) {
            s  += __shfl_xor_sync(0xffffffffu, s, of);
            ss += __shfl_xor_sync(0xffffffffu, ss, of);
        }
        if (lane == 0) { rs_[0] = s; rss_[0] = ss; }
    }
    __syncthreads();
    const float mu  = rs_[0] * (1.0f / 1024.0f);
    const float var = rss_[0] * (1.0f / 1024.0f) - mu * mu;
    const float rstd = rsqrtf(var + 1e-5f);

    float4 wv = ((const float4*)w)[tid];
    float4 bv = ((const float4*)b)[tid];
    float o0 = (v.x - mu) * rstd * wv.x + bv.x;
    float o1 = (v.y - mu) * rstd * wv.y + bv.y;
    float o2 = (v.z - mu) * rstd * wv.z + bv.z;
    float o3 = (v.w - mu) * rstd * wv.w + bv.w;

    __half2* op = (__half2*)(o + (size_t)row * 1024 + tid * 4);
    op[0] = __halves2half2(__float2half_rn(o0), __float2half_rn(o1));
    op[1] = __halves2half2(__float2half_rn(o2), __float2half_rn(o3));
}

// --------------------- fp32 -> fp16 converters / padders -------------------
__global__ __launch_bounds__(256)
void wcvt_k(const float4* __restrict__ src, __half2* __restrict__ dst, int n4)
{
    int i = blockIdx.x * blockDim.x + threadIdx.x;
    if (i >= n4) return;
    float4 v = src[i];
    dst[i * 2 + 0] = __halves2half2(__float2half_rn(v.x), __float2half_rn(v.y));
    dst[i * 2 + 1] = __halves2half2(__float2half_rn(v.z), __float2half_rn(v.w));
}

// dst [rows, dstC] fp16, zero-padded from src [srcR, srcC] fp32.
__global__ __launch_bounds__(256)
void padcvt_k(const float* __restrict__ src, __half* __restrict__ dst,
              int rows, int srcR, int srcC, int dstC)
{
    int i = blockIdx.x * blockDim.x + threadIdx.x;
    if (i >= rows * dstC) return;
    int r = i / dstC, c = i - r * dstC;
    float v = (r < srcR && c < srcC) ? src[(size_t)r * srcC + c] : 0.0f;
    dst[i] = __float2half_rn(v);
}

__global__ __launch_bounds__(256)
void padbias_k(const float* __restrict__ src, float* __restrict__ dst,
               int srcN, int dstN)
{
    int i = blockIdx.x * blockDim.x + threadIdx.x;
    if (i < dstN) dst[i] = (i < srcN) ? src[i] : 0.0f;
}

// ------------------------------- host side ---------------------------------
static inline int cdiv(int a, int b) { return (a + b - 1) / b; }

extern "C" void kernel_launch(void* const* d_in, const int* in_sizes, int n_in,
                              void* d_out, int out_size)
{
    const float* x       = (const float*)d_in[0];
    const float* embed_w = (const float*)d_in[1];
    const float* embed_b = (const float*)d_in[2];
    const float* W1_w    = (const float*)d_in[3];
    const float* W1_b    = (const float*)d_in[4];
    const float* W2_w    = (const float*)d_in[5];
    const float* W2_b    = (const float*)d_in[6];
    const float* norm_w  = (const float*)d_in[7];
    const float* norm_b  = (const float*)d_in[8];
    const float* head_w  = (const float*)d_in[9];
    const float* head_b  = (const float*)d_in[10];
    float* out = (float*)d_out;
    (void)in_sizes; (void)n_in; (void)out_size;

    float *xemb, *h, *hbp;
    __half *hn, *t, *w1h, *w2h, *xp, *ewp, *hwp, *hf;
    cudaGetSymbolAddress((void**)&xemb, g_xemb);
    cudaGetSymbolAddress((void**)&h,    g_h);
    cudaGetSymbolAddress((void**)&hn,   g_hn);
    cudaGetSymbolAddress((void**)&t,    g_t);
    cudaGetSymbolAddress((void**)&w1h,  g_w1h);
    cudaGetSymbolAddress((void**)&w2h,  g_w2h);
    cudaGetSymbolAddress((void**)&xp,   g_xp);
    cudaGetSymbolAddress((void**)&ewp,  g_ewp);
    cudaGetSymbolAddress((void**)&hwp,  g_hwp);
    cudaGetSymbolAddress((void**)&hbp,  g_hbp);
    cudaGetSymbolAddress((void**)&hf,   g_hf);

    cudaFuncSetAttribute(tgemm_mma<0, 0>,
                         cudaFuncAttributeMaxDynamicSharedMemorySize, MSMEM_B);
    cudaFuncSetAttribute(tgemm_mma<1, 0>,
                         cudaFuncAttributeMaxDynamicSharedMemorySize, MSMEM_B);
    cudaFuncSetAttribute(tgemm_mma<2, 0>,
                         cudaFuncAttributeMaxDynamicSharedMemorySize, MSMEM_B);
    cudaFuncSetAttribute(tgemm_mma<3, 1000>,
                         cudaFuncAttributeMaxDynamicSharedMemorySize, MSMEM_B);

    // Weight conversions / pads (fixed cost per call).
    {
        int n4 = (FFN * HDIM) / 4;
        wcvt_k<<<cdiv(n4, 256), 256>>>((const float4*)W1_w, (__half2*)w1h, n4);
        wcvt_k<<<cdiv(n4, 256), 256>>>((const float4*)W2_w, (__half2*)w2h, n4);
        padcvt_k<<<cdiv(BATCH * DINP, 256), 256>>>(x, xp, BATCH, BATCH, DIN, DINP);
        padcvt_k<<<cdiv(HDIM * DINP, 256), 256>>>(embed_w, ewp, HDIM, HDIM, DIN, DINP);
        padcvt_k<<<cdiv(HDIM * HDIM, 256), 256>>>(head_w, hwp, HDIM, DOUT, HDIM, HDIM);
        padbias_k<<<4, 256>>>(head_b, hbp, DOUT, HDIM);
    }

    // embed: xemb = h0 = x @ embed_w^T + embed_b   (fp16 MMA, K=800)
    {
        dim3 grid(HDIM / 128, BATCH / 128);
        tgemm_mma<2, 0><<<grid, 256, MSMEM_B>>>(xp, ewp, DINP, HDIM, embed_b,
                                                xemb, h, nullptr, nullptr);
    }

    for (int s = 0; s < STEPS; s++) {
        layernorm_k<<<BATCH, 256>>>(h, norm_w, norm_b, hn);

        // t = tanh(hn @ W1^T + b1)  [4096, 4096] fp16
        {
            dim3 grid(FFN / 128, BATCH / 128);
            tgemm_mma<0, 0><<<grid, 256, MSMEM_B>>>(hn, w1h, HDIM, FFN, W1_b,
                                                    nullptr, nullptr, nullptr, t);
        }
        // h = 0.5*h + 0.5*(t @ W2^T + b2 + x_emb)  [4096, 1024]
        {
            dim3 grid(HDIM / 128, BATCH / 128);
            tgemm_mma<1, 0><<<grid, 256, MSMEM_B>>>(t, w2h, FFN, HDIM, W2_b,
                                                    h, nullptr, xemb, nullptr);
        }
    }

    // h -> fp16, then out = h @ head_w^T + head_b  (guarded N=1000)
    {
        int n4 = (BATCH * HDIM) / 4;
        wcvt_k<<<cdiv(n4, 256), 256>>>((const float4*)h, (__half2*)hf, n4);
        dim3 grid(HDIM / 128, BATCH / 128);
        tgemm_mma<3, 1000><<<grid, 256, MSMEM_B>>>(hf, hwp, HDIM, HDIM, hbp,
                                                   out, nullptr, nullptr, nullptr);
    }
}